// round 7
// baseline (speedup 1.0000x reference)
#include <cuda_runtime.h>

// DiarizationLoss: B=32, T=65536, S=4, scalar output. Single fused kernel.

#define NB 32
#define NT 65536
#define CEPS 1e-7f
#define LN2F 0.69314718055994531f

#define CHUNKS 16
#define THREADS 256
#define CHUNK_T (NT / CHUNKS)              // 4096
#define GROUPS (CHUNK_T / (THREADS * 2))   // 8 groups of 2 elements per thread
#define GRID (NB * CHUNKS)                 // 512 blocks = one wave @4/SM

__device__ float g_part[NB][21];
__device__ unsigned int g_count;

// lengths dtype probe: values in [32768,65536), nonzero.
// int64 LE => word1 (hi of lengths[0]) == 0 ; int32 => word1 >= 32768.
__device__ __forceinline__ int load_len(const int* __restrict__ p32, int b) {
    return (p32[1] == 0) ? p32[2 * b] : p32[b];
}

__global__ __launch_bounds__(THREADS, 4) void diar_loss_kernel(
    const float* __restrict__ ps,
    const float* __restrict__ pv,
    const float* __restrict__ lb,
    const float* __restrict__ vad,
    const int*   __restrict__ len32,
    float*       __restrict__ out)
{
    const int b     = blockIdx.x >> 4;           // / CHUNKS
    const int chunk = blockIdx.x & (CHUNKS - 1);
    const int len   = load_len(len32, b);
    const int t0    = chunk * CHUNK_T;

    if (t0 < len) {
        float acc[21];
        #pragma unroll
        for (int k = 0; k < 21; k++) acc[k] = 0.0f;

        const float4* __restrict__ psb  = (const float4*)(ps + (size_t)b * NT * 4);
        const float4* __restrict__ lbb  = (const float4*)(lb + (size_t)b * NT * 4);
        const float2* __restrict__ pv2b = (const float2*)(pv  + (size_t)b * NT);
        const float2* __restrict__ v2b  = (const float2*)(vad + (size_t)b * NT);

        // base-2 logs; ln2 folded into finalize. m in {0,1} applies the length mask.
        auto elem = [&](float4 p4, float4 l4, float pvv, float v, float m) {
            float pp[4] = {p4.x, p4.y, p4.z, p4.w};
            float ll[4] = {l4.x * m, l4.y * m, l4.z * m, l4.w * m};
            float d[4];
            #pragma unroll
            for (int i = 0; i < 4; i++) {
                float p  = fminf(fmaxf(pp[i], CEPS), 1.0f - CEPS);
                float lq = __log2f(1.0f - p);
                float lp = __log2f(p);
                d[i] = lp - lq;
                acc[16 + i] += lq * m;
            }
            #pragma unroll
            for (int i = 0; i < 4; i++)
                #pragma unroll
                for (int j = 0; j < 4; j++)
                    acc[i * 4 + j] += d[i] * ll[j];
            pvv = fminf(fmaxf(pvv, CEPS), 1.0f - CEPS);
            float arg = (v > 0.5f) ? pvv : (1.0f - pvv);
            acc[20] -= __log2f(arg) * m;
        };

        // uniform pipelined path for ALL non-skipped chunks (mask handles tail)
        const int base = t0 + 2 * threadIdx.x;
        #pragma unroll 2
        for (int g = 0; g < GROUPS; g++) {
            const int t = base + g * (THREADS * 2);
            float4 P0 = psb[t],  P1 = psb[t + 1];
            float4 L0 = lbb[t],  L1 = lbb[t + 1];
            float2 pv2 = pv2b[t >> 1];
            float2 v2  = v2b[t >> 1];
            float m0 = (t     < len) ? 1.0f : 0.0f;
            float m1 = (t + 1 < len) ? 1.0f : 0.0f;
            elem(P0, L0, pv2.x, v2.x, m0);
            elem(P1, L1, pv2.y, v2.y, m1);
        }

        // warp reduce -> lane0 REDG per value (no smem stage)
        #pragma unroll
        for (int k = 0; k < 21; k++) {
            float v = acc[k];
            v += __shfl_down_sync(0xffffffffu, v, 16);
            v += __shfl_down_sync(0xffffffffu, v, 8);
            v += __shfl_down_sync(0xffffffffu, v, 4);
            v += __shfl_down_sync(0xffffffffu, v, 2);
            v += __shfl_down_sync(0xffffffffu, v, 1);
            acc[k] = v;
        }
        if ((threadIdx.x & 31) == 0) {
            #pragma unroll
            for (int k = 0; k < 21; k++)
                atomicAdd(&g_part[b][k], acc[k]);
        }
    }

    // ---- last-block finalize ----
    __shared__ int s_last;
    if (threadIdx.x == 0) {
        __threadfence();
        unsigned prev = atomicAdd(&g_count, 1u);
        s_last = (prev == (unsigned)(GRID - 1));
    }
    __syncthreads();
    if (!s_last) return;
    __threadfence();

    if (threadIdx.x < NB) {
        const int bb = threadIdx.x;
        const float msum = (float)load_len(len32, bb);
        const float scal = LN2F / msum;   // fold ln2 (base-2 logs) here

        float L[4][4];
        #pragma unroll
        for (int i = 0; i < 4; i++)
            #pragma unroll
            for (int j = 0; j < 4; j++)
                L[i][j] = -(g_part[bb][i * 4 + j] + g_part[bb][16 + i]) * scal;

        float best = 3.4e38f;
        #pragma unroll
        for (int a = 0; a < 4; a++)
            #pragma unroll
            for (int cc = 0; cc < 4; cc++) {
                if (cc == a) continue;
                #pragma unroll
                for (int e = 0; e < 4; e++) {
                    if (e == a || e == cc) continue;
                    int f = 6 - a - cc - e;
                    best = fminf(best, L[0][a] + L[1][cc] + L[2][e] + L[3][f]);
                }
            }
        best *= 0.25f;

        float sb = best, sv = g_part[bb][20] * LN2F, sd = msum;
        #pragma unroll
        for (int off = 16; off >= 1; off >>= 1) {
            sb += __shfl_xor_sync(0xffffffffu, sb, off);
            sv += __shfl_xor_sync(0xffffffffu, sv, off);
            sd += __shfl_xor_sync(0xffffffffu, sd, off);
        }
        if (bb == 0)
            out[0] = (sb / (float)NB) + 0.5f * (sv / sd);
    }
    __syncthreads();

    // reset scratch for next graph replay
    for (int i = threadIdx.x; i < NB * 21; i += THREADS)
        ((float*)g_part)[i] = 0.0f;
    if (threadIdx.x == 0) g_count = 0u;
}

extern "C" void kernel_launch(void* const* d_in, const int* in_sizes, int n_in,
                              void* d_out, int out_size)
{
    diar_loss_kernel<<<GRID, THREADS>>>(
        (const float*)d_in[0], (const float*)d_in[1],
        (const float*)d_in[2], (const float*)d_in[3],
        (const int*)d_in[4], (float*)d_out);
}